// round 16
// baseline (speedup 1.0000x reference)
#include <cuda_runtime.h>
#include <cuda_bf16.h>
#include <cstdint>

// Problem dims (fixed)
static constexpr int T = 1024, B = 32, S = 2048, D = 512;
static constexpr float LN_EPS = 1e-6f;

// ---------------------------------------------------------------------------
// Scratch (device globals; no runtime allocation)
// ---------------------------------------------------------------------------
__device__ __align__(256) float g_X[(size_t)B * T * D];                 // linear out fp32
__device__ __align__(256) __nv_bfloat16 g_Xh[(size_t)B * T * D];
__device__ __align__(256) __nv_bfloat16 g_Xl[(size_t)B * T * D];
__device__ __align__(256) __nv_bfloat16 g_inph[(size_t)T * B * D];
__device__ __align__(256) __nv_bfloat16 g_inpl[(size_t)T * B * D];
__device__ __align__(256) __nv_bfloat16 g_Wh[(size_t)D * D];
__device__ __align__(256) __nv_bfloat16 g_Wl[(size_t)D * D];
__device__ __align__(256) __nv_bfloat16 g_ctxh[(size_t)B * S * D];
__device__ __align__(256) __nv_bfloat16 g_ctxl[(size_t)B * S * D];
__device__ __align__(256) uint32_t g_vkph[(size_t)B * (S / 2) * D];     // bf16x2 k-pairs
__device__ __align__(256) uint32_t g_vkpl[(size_t)B * (S / 2) * D];
__device__ __align__(256) __nv_bfloat16 g_attnh[(size_t)B * T * S];
__device__ __align__(256) __nv_bfloat16 g_attnl[(size_t)B * T * S];

// ---------------------------------------------------------------------------
__device__ __forceinline__ void mma16(float* d, const uint32_t* a, const uint32_t* b) {
    asm volatile(
        "mma.sync.aligned.m16n8k16.row.col.f32.bf16.bf16.f32 "
        "{%0,%1,%2,%3}, {%4,%5,%6,%7}, {%8,%9}, {%0,%1,%2,%3};"
        : "+f"(d[0]), "+f"(d[1]), "+f"(d[2]), "+f"(d[3])
        : "r"(a[0]), "r"(a[1]), "r"(a[2]), "r"(a[3]), "r"(b[0]), "r"(b[1]));
}
__device__ __forceinline__ uint32_t packbf(float x, float y) {
    __nv_bfloat162 t = __floats2bfloat162_rn(x, y);
    return *reinterpret_cast<uint32_t*>(&t);
}
__device__ __forceinline__ void ldsm_x4(uint32_t& r0, uint32_t& r1, uint32_t& r2,
                                        uint32_t& r3, uint32_t addr) {
    asm volatile("ldmatrix.sync.aligned.m8n8.x4.shared.b16 {%0,%1,%2,%3}, [%4];"
                 : "=r"(r0), "=r"(r1), "=r"(r2), "=r"(r3) : "r"(addr));
}
__device__ __forceinline__ void cpa16(uint32_t dst, const void* src) {
    asm volatile("cp.async.cg.shared.global [%0], [%1], 16;" :: "r"(dst), "l"(src) : "memory");
}
__device__ __forceinline__ void cpa_commit() {
    asm volatile("cp.async.commit_group;" ::: "memory");
}
__device__ __forceinline__ void cpa_wait1() {
    asm volatile("cp.async.wait_group 1;" ::: "memory");
}
__device__ __forceinline__ void cpa_wait0() {
    asm volatile("cp.async.wait_group 0;" ::: "memory");
}

static constexpr int KC = 32;

// ---------------------------------------------------------------------------
// Pre-split kernels: fp32 -> bf16 hi/lo (src passed by value — graph-safe)
// ---------------------------------------------------------------------------
__global__ void k_split(const float* __restrict__ src, int which, size_t n4) {
    size_t i = (size_t)blockIdx.x * blockDim.x + threadIdx.x;
    if (i >= n4) return;
    __nv_bfloat16 *h, *l;
    if (which == 0) { h = g_inph; l = g_inpl; }
    else if (which == 1) { h = g_Wh; l = g_Wl; }
    else { h = g_ctxh; l = g_ctxl; }
    float4 v = reinterpret_cast<const float4*>(src)[i];
    __nv_bfloat16 h0 = __float2bfloat16(v.x);
    __nv_bfloat16 h1 = __float2bfloat16(v.y);
    __nv_bfloat16 h2 = __float2bfloat16(v.z);
    __nv_bfloat16 h3 = __float2bfloat16(v.w);
    uint2 hp, lp;
    __nv_bfloat162 t0 = {h0, h1}; hp.x = *reinterpret_cast<uint32_t*>(&t0);
    __nv_bfloat162 t1 = {h2, h3}; hp.y = *reinterpret_cast<uint32_t*>(&t1);
    lp.x = packbf(v.x - __bfloat162float(h0), v.y - __bfloat162float(h1));
    lp.y = packbf(v.z - __bfloat162float(h2), v.w - __bfloat162float(h3));
    reinterpret_cast<uint2*>(h)[i] = hp;
    reinterpret_cast<uint2*>(l)[i] = lp;
}

// values -> k-pair-interleaved bf16x2 words:
// g_vkp[(b*(S/2)+kp)*D + d] = pack(v[2kp][d], v[2kp+1][d])
__global__ void k_vkp(const float* __restrict__ v) {
    size_t i = (size_t)blockIdx.x * blockDim.x + threadIdx.x;   // over B*(S/2)*(D/4)
    const size_t total = (size_t)B * (S / 2) * (D / 4);
    if (i >= total) return;
    const size_t d4 = i % (D / 4);
    const size_t rest = i / (D / 4);
    const size_t kp = rest % (S / 2);
    const size_t b = rest / (S / 2);
    const float* r0 = v + ((b * S + 2 * kp) * D) + d4 * 4;
    float4 a = *reinterpret_cast<const float4*>(r0);
    float4 c = *reinterpret_cast<const float4*>(r0 + D);
    const float e0[4] = {a.x, a.y, a.z, a.w};
    const float e1[4] = {c.x, c.y, c.z, c.w};
    uint4 hw, lw;
    uint32_t* hwp = reinterpret_cast<uint32_t*>(&hw);
    uint32_t* lwp = reinterpret_cast<uint32_t*>(&lw);
    #pragma unroll
    for (int q = 0; q < 4; q++) {
        __nv_bfloat16 h0 = __float2bfloat16(e0[q]);
        __nv_bfloat16 h1 = __float2bfloat16(e1[q]);
        __nv_bfloat162 th = {h0, h1};
        hwp[q] = *reinterpret_cast<uint32_t*>(&th);
        lwp[q] = packbf(e0[q] - __bfloat162float(h0), e1[q] - __bfloat162float(h1));
    }
    const size_t w = (b * (S / 2) + kp) * D + d4 * 4;
    *reinterpret_cast<uint4*>(g_vkph + w) = hw;
    *reinterpret_cast<uint4*>(g_vkpl + w) = lw;
}

// ---------------------------------------------------------------------------
// NT split-BF16 GEMM: C[M,N] = A[M,K]*B[N,K]^T, K=512, KC=32. 128x128, 256 thr.
// Operands pre-split bf16 hi/lo in global. Producer = cp.async 16B copies.
// 2-stage async pipeline, ldmatrix consumers, staged split passes, 2 CTAs/SM.
// MODE 0: linear (A=inp split, B=W split, C=g_X fp32)
// MODE 1: scores (A=g_X split, B=ctx split, C=attn fp32)
// ---------------------------------------------------------------------------
static constexpr int SC_PAD = 40;                        // halves per row
static constexpr int SC_REG = 128 * SC_PAD;              // 5120 halves / region
static constexpr int SC_STAGE = 4 * SC_REG;              // 20480 halves
static constexpr int SC_SMEM = 2 * SC_STAGE * 2;         // 81920 bytes

template <int MODE>
__global__ __launch_bounds__(256, 2) void k_gemm_nt(float* __restrict__ Cp) {
    extern __shared__ __nv_bfloat16 smh[];
    constexpr int NC = D / KC;   // 16

    const int tid = threadIdx.x;
    const int n0 = blockIdx.x * 128;
    const int m0 = blockIdx.y * 128;
    const int bz = blockIdx.z;

    const __nv_bfloat16 *Ah, *Al, *Bh, *Bl;
    size_t a_rs;
    float* Cbase; size_t c_rs;
    if (MODE == 0) {
        const int bb = m0 >> 10, t0 = m0 & 1023;
        const size_t ao = ((size_t)t0 * B + bb) * D;
        Ah = g_inph + ao; Al = g_inpl + ao; a_rs = (size_t)B * D;
        Bh = g_Wh + (size_t)n0 * D; Bl = g_Wl + (size_t)n0 * D;
        Cbase = g_X + (size_t)m0 * D + n0; c_rs = D;
    } else {
        const size_t ao = ((size_t)bz * T + m0) * D;
        Ah = g_Xh + ao; Al = g_Xl + ao; a_rs = D;
        const size_t bo = ((size_t)bz * S + n0) * D;
        Bh = g_ctxh + bo; Bl = g_ctxl + bo;
        Cbase = Cp + ((size_t)bz * T + m0) * S + n0; c_rs = S;
    }

    const int lane = tid & 31, wid = tid >> 5;
    const int gr = lane >> 2, gc = lane & 3;
    const int m_w = (wid >> 2) * 64;
    const int n_w = (wid & 3) * 32;

    // ldmatrix lane-address components (validated in R14)
    const uint32_t aRow = (uint32_t)(m_w + (lane & 15));
    const uint32_t aColSel = (uint32_t)((lane >> 4) * 8);
    const uint32_t bRowOff = (uint32_t)(((lane >> 4) & 1) * 8 + (lane & 7));
    const uint32_t bColSel = (uint32_t)(((lane >> 3) & 1) * 8);

    const uint32_t smem_b = (uint32_t)__cvta_generic_to_shared(smh);

    auto produce = [&](int c, int s) {
        const int k0 = c * KC;
        const uint32_t sb = smem_b + (uint32_t)(s * SC_STAGE) * 2u;
        #pragma unroll
        for (int j = 0; j < 2; j++) {
            const int id = tid * 2 + j;            // 0..511
            const int row = id >> 2, seg = id & 3;
            const uint32_t doff = (uint32_t)(row * SC_PAD + seg * 8) * 2u;
            const size_t aoff = (size_t)row * a_rs + k0 + seg * 8;
            const size_t boff = (size_t)row * D + k0 + seg * 8;
            cpa16(sb + doff, Ah + aoff);
            cpa16(sb + (uint32_t)SC_REG * 2u + doff, Al + aoff);
            cpa16(sb + (uint32_t)SC_REG * 4u + doff, Bh + boff);
            cpa16(sb + (uint32_t)SC_REG * 6u + doff, Bl + boff);
        }
    };

    float acc[4][4][4];
    #pragma unroll
    for (int i = 0; i < 4; i++)
        #pragma unroll
        for (int j = 0; j < 4; j++)
            #pragma unroll
            for (int q = 0; q < 4; q++) acc[i][j][q] = 0.f;

    produce(0, 0);
    cpa_commit();

    for (int c = 0; c < NC; c++) {
        const int s = c & 1;
        if (c + 1 < NC) {
            produce(c + 1, s ^ 1);
            cpa_commit();
            cpa_wait1();
        } else {
            cpa_wait0();
        }
        __syncthreads();

        const uint32_t bAh = smem_b + (uint32_t)(s * SC_STAGE) * 2u;
        const uint32_t bAl = bAh + (uint32_t)SC_REG * 2u;
        const uint32_t bBh = bAl + (uint32_t)SC_REG * 2u;
        const uint32_t bBl = bBh + (uint32_t)SC_REG * 2u;

        #pragma unroll
        for (int ks = 0; ks < 2; ks++) {
            uint32_t ah[4][4], bh[4][2];
            #pragma unroll
            for (int mf = 0; mf < 4; mf++) {
                const uint32_t off =
                    ((aRow + mf * 16u) * SC_PAD + (uint32_t)(ks * 16) + aColSel) * 2u;
                ldsm_x4(ah[mf][0], ah[mf][1], ah[mf][2], ah[mf][3], bAh + off);
            }
            #pragma unroll
            for (int p = 0; p < 2; p++) {
                const uint32_t off =
                    (((uint32_t)n_w + p * 16u + bRowOff) * SC_PAD +
                     (uint32_t)(ks * 16) + bColSel) * 2u;
                ldsm_x4(bh[2 * p][0], bh[2 * p][1], bh[2 * p + 1][0], bh[2 * p + 1][1],
                        bBh + off);
            }
            #pragma unroll
            for (int mf = 0; mf < 4; mf++)
                #pragma unroll
                for (int nf = 0; nf < 4; nf++)
                    mma16(acc[mf][nf], ah[mf], bh[nf]);
            {
                uint32_t al[4][4];
                #pragma unroll
                for (int mf = 0; mf < 4; mf++) {
                    const uint32_t off =
                        ((aRow + mf * 16u) * SC_PAD + (uint32_t)(ks * 16) + aColSel) * 2u;
                    ldsm_x4(al[mf][0], al[mf][1], al[mf][2], al[mf][3], bAl + off);
                }
                #pragma unroll
                for (int mf = 0; mf < 4; mf++)
                    #pragma unroll
                    for (int nf = 0; nf < 4; nf++)
                        mma16(acc[mf][nf], al[mf], bh[nf]);
            }
            {
                uint32_t bl[4][2];
                #pragma unroll
                for (int p = 0; p < 2; p++) {
                    const uint32_t off =
                        (((uint32_t)n_w + p * 16u + bRowOff) * SC_PAD +
                         (uint32_t)(ks * 16) + bColSel) * 2u;
                    ldsm_x4(bl[2 * p][0], bl[2 * p][1], bl[2 * p + 1][0], bl[2 * p + 1][1],
                            bBl + off);
                }
                #pragma unroll
                for (int mf = 0; mf < 4; mf++)
                    #pragma unroll
                    for (int nf = 0; nf < 4; nf++)
                        mma16(acc[mf][nf], ah[mf], bl[nf]);
            }
        }
        __syncthreads();
    }

    #pragma unroll
    for (int mf = 0; mf < 4; mf++)
        #pragma unroll
        for (int nf = 0; nf < 4; nf++) {
            const int mrow = m_w + mf * 16 + gr;
            const int ncol = n_w + nf * 8 + 2 * gc;
            float2 v0 = make_float2(acc[mf][nf][0], acc[mf][nf][1]);
            float2 v1 = make_float2(acc[mf][nf][2], acc[mf][nf][3]);
            *reinterpret_cast<float2*>(Cbase + (size_t)mrow * c_rs + ncol) = v0;
            *reinterpret_cast<float2*>(Cbase + (size_t)(mrow + 8) * c_rs + ncol) = v1;
        }
}

// ---------------------------------------------------------------------------
// AV GEMM: out[t][b][d] = sum_s attn[b][t][s]*values[b][s][d]  (bf16x3)
// A = g_attnh/l (pre-split), B = g_vkph/l (pre-packed k-pairs). All cp.async.
// ---------------------------------------------------------------------------
static constexpr int AV_A_WPAD = 20;                       // words per A row
static constexpr int AV_A_WORDS = 128 * AV_A_WPAD;         // 2560
static constexpr int AV_B_WPAD = 136;                      // words per kp row
static constexpr int AV_B_WORDS = 16 * AV_B_WPAD;          // 2176
static constexpr int AV_STAGE_WORDS = 2 * AV_A_WORDS + 2 * AV_B_WORDS;  // 9472
static constexpr int AV_SMEM = 2 * AV_STAGE_WORDS * 4;     // 75776 bytes

__global__ __launch_bounds__(256, 2) void k_gemm_av(float* __restrict__ out) {
    extern __shared__ uint32_t smw[];
    constexpr int NC = S / KC;   // 64

    const int tid = threadIdx.x;
    const int n0 = blockIdx.x * 128;
    const int m0 = blockIdx.y * 128;
    const int bz = blockIdx.z;

    const __nv_bfloat16* Ah = g_attnh + ((size_t)bz * T + m0) * S;
    const __nv_bfloat16* Al = g_attnl + ((size_t)bz * T + m0) * S;
    const uint32_t* Bh = g_vkph + (size_t)bz * (S / 2) * D + n0;
    const uint32_t* Bl = g_vkpl + (size_t)bz * (S / 2) * D + n0;
    float* Cbase = out + (size_t)m0 * B * D + (size_t)bz * D + n0;
    const size_t c_rs = (size_t)B * D;

    const int lane = tid & 31, wid = tid >> 5;
    const int gr = lane >> 2, gc = lane & 3;
    const int m_w = (wid >> 2) * 64;
    const int n_w = (wid & 3) * 32;

    const uint32_t aRow = (uint32_t)(m_w + (lane & 15));
    const uint32_t aColSel = (uint32_t)((lane >> 4) * 8);

    const uint32_t smem_b = (uint32_t)__cvta_generic_to_shared(smw);

    auto produce = [&](int c, int s) {
        const int k0 = c * KC;
        const uint32_t sb = smem_b + (uint32_t)(s * AV_STAGE_WORDS) * 4u;
        #pragma unroll
        for (int j = 0; j < 2; j++) {
            const int id = tid * 2 + j;          // A: 0..511
            const int row = id >> 2, seg = id & 3;
            const uint32_t doff = (uint32_t)(row * AV_A_WPAD + seg * 4) * 4u;
            const size_t aoff = (size_t)row * S + k0 + seg * 8;
            cpa16(sb + doff, Ah + aoff);
            cpa16(sb + (uint32_t)AV_A_WORDS * 4u + doff, Al + aoff);
        }
        const uint32_t sbB = sb + (uint32_t)(2 * AV_A_WORDS) * 4u;
        #pragma unroll
        for (int j = 0; j < 2; j++) {
            const int id = tid * 2 + j;          // B: 0..511
            const int kpr = id >> 5, seg = id & 31;
            const uint32_t doff = (uint32_t)(kpr * AV_B_WPAD + seg * 4) * 4u;
            const size_t boff = (size_t)(k0 / 2 + kpr) * D + seg * 4;
            cpa16(sbB + doff, Bh + boff);
            cpa16(sbB + (uint32_t)AV_B_WORDS * 4u + doff, Bl + boff);
        }
    };

    float acc[4][4][4];
    #pragma unroll
    for (int i = 0; i < 4; i++)
        #pragma unroll
        for (int j = 0; j < 4; j++)
            #pragma unroll
            for (int q = 0; q < 4; q++) acc[i][j][q] = 0.f;

    produce(0, 0);
    cpa_commit();

    for (int c = 0; c < NC; c++) {
        const int s = c & 1;
        if (c + 1 < NC) {
            produce(c + 1, s ^ 1);
            cpa_commit();
            cpa_wait1();
        } else {
            cpa_wait0();
        }
        __syncthreads();

        const uint32_t bAh = smem_b + (uint32_t)(s * AV_STAGE_WORDS) * 4u;
        const uint32_t bAl = bAh + (uint32_t)AV_A_WORDS * 4u;
        const uint32_t* sBh = smw + s * AV_STAGE_WORDS + 2 * AV_A_WORDS;
        const uint32_t* sBl = sBh + AV_B_WORDS;

        #pragma unroll
        for (int ks = 0; ks < 2; ks++) {
            uint32_t ah[4][4], bh[4][2];
            #pragma unroll
            for (int mf = 0; mf < 4; mf++) {
                const uint32_t off =
                    ((aRow + mf * 16u) * 40u + (uint32_t)(ks * 16) + aColSel) * 2u;
                ldsm_x4(ah[mf][0], ah[mf][1], ah[mf][2], ah[mf][3], bAh + off);
            }
            #pragma unroll
            for (int nf = 0; nf < 4; nf++) {
                const int n = n_w + nf * 8 + gr;
                bh[nf][0] = sBh[(ks * 8 + gc) * AV_B_WPAD + n];
                bh[nf][1] = sBh[(ks * 8 + gc + 4) * AV_B_WPAD + n];
            }
            #pragma unroll
            for (int mf = 0; mf < 4; mf++)
                #pragma unroll
                for (int nf = 0; nf < 4; nf++)
                    mma16(acc[mf][nf], ah[mf], bh[nf]);
            {
                uint32_t al[4][4];
                #pragma unroll
                for (int mf = 0; mf < 4; mf++) {
                    const uint32_t off =
                        ((aRow + mf * 16u) * 40u + (uint32_t)(ks * 16) + aColSel) * 2u;
                    ldsm_x4(al[mf][0], al[mf][1], al[mf][2], al[mf][3], bAl + off);
                }
                #pragma unroll
                for (int mf = 0; mf < 4; mf++)
                    #pragma unroll
                    for (int nf = 0; nf < 4; nf++)
                        mma16(acc[mf][nf], al[mf], bh[nf]);
            }
            {
                uint32_t bl[4][2];
                #pragma unroll
                for (int nf = 0; nf < 4; nf++) {
                    const int n = n_w + nf * 8 + gr;
                    bl[nf][0] = sBl[(ks * 8 + gc) * AV_B_WPAD + n];
                    bl[nf][1] = sBl[(ks * 8 + gc + 4) * AV_B_WPAD + n];
                }
                #pragma unroll
                for (int mf = 0; mf < 4; mf++)
                    #pragma unroll
                    for (int nf = 0; nf < 4; nf++)
                        mma16(acc[mf][nf], ah[mf], bl[nf]);
            }
        }
        __syncthreads();
    }

    #pragma unroll
    for (int mf = 0; mf < 4; mf++)
        #pragma unroll
        for (int nf = 0; nf < 4; nf++) {
            const int mrow = m_w + mf * 16 + gr;
            const int ncol = n_w + nf * 8 + 2 * gc;
            float2 v0 = make_float2(acc[mf][nf][0], acc[mf][nf][1]);
            float2 v1 = make_float2(acc[mf][nf][2], acc[mf][nf][3]);
            *reinterpret_cast<float2*>(Cbase + (size_t)mrow * c_rs + ncol) = v0;
            *reinterpret_cast<float2*>(Cbase + (size_t)(mrow + 8) * c_rs + ncol) = v1;
        }
}

// ---------------------------------------------------------------------------
// LayerNorm: reads g_X fp32, writes split bf16 g_Xh/g_Xl
// ---------------------------------------------------------------------------
__global__ __launch_bounds__(256) void k_ln(const float* __restrict__ gamma,
                                            const float* __restrict__ beta) {
    const int row = blockIdx.x;
    const float* x = &g_X[(size_t)row * D];
    const int tid = threadIdx.x;

    float2 v = *reinterpret_cast<const float2*>(&x[tid * 2]);
    float s = v.x + v.y;
    float q = v.x * v.x + v.y * v.y;

    __shared__ float sh_s[8], sh_q[8];
    #pragma unroll
    for (int o = 16; o > 0; o >>= 1) {
        s += __shfl_xor_sync(0xffffffffu, s, o);
        q += __shfl_xor_sync(0xffffffffu, q, o);
    }
    if ((tid & 31) == 0) { sh_s[tid >> 5] = s; sh_q[tid >> 5] = q; }
    __syncthreads();
    float ts = 0.f, tq = 0.f;
    #pragma unroll
    for (int i = 0; i < 8; i++) { ts += sh_s[i]; tq += sh_q[i]; }

    const float mean = ts * (1.0f / D);
    const float var = tq * (1.0f / D) - mean * mean;
    const float rstd = rsqrtf(var + LN_EPS);

    float2 g = *reinterpret_cast<const float2*>(&gamma[tid * 2]);
    float2 bb = *reinterpret_cast<const float2*>(&beta[tid * 2]);
    float ox = g.x * (v.x - mean) * rstd + bb.x;
    float oy = g.y * (v.y - mean) * rstd + bb.y;

    __nv_bfloat16 h0 = __float2bfloat16(ox);
    __nv_bfloat16 h1 = __float2bfloat16(oy);
    __nv_bfloat162 hp = {h0, h1};
    uint32_t lpw = packbf(ox - __bfloat162float(h0), oy - __bfloat162float(h1));
    reinterpret_cast<uint32_t*>(g_Xh + (size_t)row * D)[tid] =
        *reinterpret_cast<uint32_t*>(&hp);
    reinterpret_cast<uint32_t*>(g_Xl + (size_t)row * D)[tid] = lpw;
}

// ---------------------------------------------------------------------------
// Softmax: in-place on attn output, also writes split bf16 g_attnh/g_attnl
// ---------------------------------------------------------------------------
__global__ __launch_bounds__(256) void k_softmax(float* __restrict__ attn) {
    const size_t row = blockIdx.x;
    float* p = attn + row * (size_t)S;
    const int tid = threadIdx.x;

    float4 v0 = reinterpret_cast<const float4*>(p)[tid * 2 + 0];
    float4 v1 = reinterpret_cast<const float4*>(p)[tid * 2 + 1];

    float m = fmaxf(fmaxf(fmaxf(v0.x, v0.y), fmaxf(v0.z, v0.w)),
                    fmaxf(fmaxf(v1.x, v1.y), fmaxf(v1.z, v1.w)));
    __shared__ float sh[8];
    #pragma unroll
    for (int o = 16; o > 0; o >>= 1) m = fmaxf(m, __shfl_xor_sync(0xffffffffu, m, o));
    if ((tid & 31) == 0) sh[tid >> 5] = m;
    __syncthreads();
    float gm = sh[0];
    #pragma unroll
    for (int i = 1; i < 8; i++) gm = fmaxf(gm, sh[i]);
    __syncthreads();

    v0.x = __expf(v0.x - gm); v0.y = __expf(v0.y - gm);
    v0.z = __expf(v0.z - gm); v0.w = __expf(v0.w - gm);
    v1.x = __expf(v1.x - gm); v1.y = __expf(v1.y - gm);
    v1.z = __expf(v1.z - gm); v1.w = __expf(v1.w - gm);

    float s = v0.x + v0.y + v0.z + v0.w + v1.x + v1.y + v1.z + v1.w;
    #pragma unroll
    for (int o = 16; o > 0; o >>= 1) s += __shfl_xor_sync(0xffffffffu, s, o);
    if ((tid & 31) == 0) sh[tid >> 5] = s;
    __syncthreads();
    float gs = 0.f;
    #pragma unroll
    for (int i = 0; i < 8; i++) gs += sh[i];
    const float inv = 1.0f / gs;

    v0.x *= inv; v0.y *= inv; v0.z *= inv; v0.w *= inv;
    v1.x *= inv; v1.y *= inv; v1.z *= inv; v1.w *= inv;
    reinterpret_cast<float4*>(p)[tid * 2 + 0] = v0;
    reinterpret_cast<float4*>(p)[tid * 2 + 1] = v1;

    // split bf16 copy for the AV GEMM
    const float e[8] = {v0.x, v0.y, v0.z, v0.w, v1.x, v1.y, v1.z, v1.w};
    uint4 hw, lw;
    uint32_t* hwp = reinterpret_cast<uint32_t*>(&hw);
    uint32_t* lwp = reinterpret_cast<uint32_t*>(&lw);
    #pragma unroll
    for (int q = 0; q < 4; q++) {
        __nv_bfloat16 h0 = __float2bfloat16(e[2 * q]);
        __nv_bfloat16 h1 = __float2bfloat16(e[2 * q + 1]);
        __nv_bfloat162 th = {h0, h1};
        hwp[q] = *reinterpret_cast<uint32_t*>(&th);
        lwp[q] = packbf(e[2 * q] - __bfloat162float(h0),
                        e[2 * q + 1] - __bfloat162float(h1));
    }
    *reinterpret_cast<uint4*>(g_attnh + row * (size_t)S + tid * 8) = hw;
    *reinterpret_cast<uint4*>(g_attnl + row * (size_t)S + tid * 8) = lw;
}

// ---------------------------------------------------------------------------
extern "C" void kernel_launch(void* const* d_in, const int* in_sizes, int n_in,
                              void* d_out, int out_size) {
    const float* inp    = (const float*)d_in[0];  // [T,B,D]
    const float* ctx    = (const float*)d_in[1];  // [B,S,D]
    const float* values = (const float*)d_in[2];  // [B,S,D]
    const float* W      = (const float*)d_in[3];  // [D,D]
    const float* gamma  = (const float*)d_in[4];  // [D]
    const float* beta   = (const float*)d_in[5];  // [D]

    float* out_wc   = (float*)d_out;                       // [T,B,D]
    float* out_attn = (float*)d_out + (size_t)T * B * D;   // [B*T,S]

    cudaFuncSetAttribute(k_gemm_nt<0>, cudaFuncAttributeMaxDynamicSharedMemorySize, SC_SMEM);
    cudaFuncSetAttribute(k_gemm_nt<1>, cudaFuncAttributeMaxDynamicSharedMemorySize, SC_SMEM);
    cudaFuncSetAttribute(k_gemm_av, cudaFuncAttributeMaxDynamicSharedMemorySize, AV_SMEM);

    // 0) pre-split operands (src pointers passed by value — graph-safe)
    {
        k_split<<<(int)(((size_t)T * B * D / 4 + 255) / 256), 256>>>(inp, 0, (size_t)T * B * D / 4);
        k_split<<<(int)(((size_t)D * D / 4 + 255) / 256), 256>>>(W, 1, (size_t)D * D / 4);
        k_split<<<(int)(((size_t)B * S * D / 4 + 255) / 256), 256>>>(ctx, 2, (size_t)B * S * D / 4);
        const size_t nv = (size_t)B * (S / 2) * (D / 4);
        k_vkp<<<(int)((nv + 255) / 256), 256>>>(values);
    }
    // 1) linear: g_X = inp @ W^T  [bf16x3, cp.async]
    {
        dim3 grid(D / 128, (B * T) / 128, 1);
        k_gemm_nt<0><<<grid, 256, SC_SMEM>>>(nullptr);
    }
    // 2) LayerNorm -> split g_Xh/g_Xl
    k_ln<<<B * T, 256>>>(gamma, beta);
    // 3) scores -> attn region  [bf16x3, cp.async]
    {
        dim3 grid(S / 128, T / 128, B);
        k_gemm_nt<1><<<grid, 256, SC_SMEM>>>(out_attn);
    }
    // 4) softmax in place + split copy
    k_softmax<<<B * T, 256>>>(out_attn);
    // 5) weightedContext  [bf16x3, cp.async]
    {
        dim3 grid(D / 128, T / 128, B);
        k_gemm_av<<<grid, 256, AV_SMEM>>>(out_wc);
    }
}

// round 17
// speedup vs baseline: 1.6681x; 1.6681x over previous
#include <cuda_runtime.h>
#include <cuda_bf16.h>
#include <cstdint>

// Problem dims (fixed)
static constexpr int T = 1024, B = 32, S = 2048, D = 512;
static constexpr float LN_EPS = 1e-6f;

// Scratch: linear+LN output [B][T][D]
__device__ __align__(256) float g_X[(size_t)B * T * D];

// ---------------------------------------------------------------------------
__device__ __forceinline__ void mma16(float* d, const uint32_t* a, const uint32_t* b) {
    asm volatile(
        "mma.sync.aligned.m16n8k16.row.col.f32.bf16.bf16.f32 "
        "{%0,%1,%2,%3}, {%4,%5,%6,%7}, {%8,%9}, {%0,%1,%2,%3};"
        : "+f"(d[0]), "+f"(d[1]), "+f"(d[2]), "+f"(d[3])
        : "r"(a[0]), "r"(a[1]), "r"(a[2]), "r"(a[3]), "r"(b[0]), "r"(b[1]));
}
__device__ __forceinline__ uint32_t packbf(float x, float y) {
    __nv_bfloat162 t = __floats2bfloat162_rn(x, y);
    return *reinterpret_cast<uint32_t*>(&t);
}

static constexpr int KC = 32;

// ---------------------------------------------------------------------------
// NT split-BF16 GEMM (bf16x3): C[M,N] = A[M,K]*B[N,K]^T, K=512, KC=32.
// MODE 0: linear  A=inp(row b*T+t), B=W,   C=g_X
// MODE 1: scores  A=g_X,            B=ctx, C=attn
// CTA tile 128x128, 256 threads, warp tile 64x32, double-buffered.
// A,B smem: bf16 [row][k], pad 40 halves per row.
// ---------------------------------------------------------------------------
static constexpr int SC_PAD = 40;                        // halves per row
static constexpr int SC_REG = 128 * SC_PAD;              // 5120 halves / region
static constexpr int SC_STAGE = 4 * SC_REG;              // 20480 halves
static constexpr int SC_SMEM = 2 * SC_STAGE * 2;         // 81920 bytes

template <int MODE>
__global__ __launch_bounds__(256) void k_gemm_nt(const float* __restrict__ Ap,
                                                 const float* __restrict__ Bp,
                                                 float* __restrict__ Cp) {
    extern __shared__ __nv_bfloat16 smh[];
    constexpr int NC = D / KC;   // 16

    const int tid = threadIdx.x;
    const int n0 = blockIdx.x * 128;
    const int m0 = blockIdx.y * 128;
    const int bz = blockIdx.z;

    const float* Abase; size_t a_rs;
    const float* Bbase;
    float* Cbase; size_t c_rs;
    if (MODE == 0) {
        const int bb = m0 >> 10, t0 = m0 & 1023;
        Abase = Ap + ((size_t)t0 * B + bb) * D; a_rs = (size_t)B * D;
        Bbase = Bp + (size_t)n0 * D;
        Cbase = g_X + (size_t)m0 * D + n0;      c_rs = D;
    } else {
        Abase = g_X + ((size_t)bz * T + m0) * D;     a_rs = D;
        Bbase = Bp + ((size_t)bz * S + n0) * D;
        Cbase = Cp + ((size_t)bz * T + m0) * S + n0; c_rs = S;
    }

    const int lane = tid & 31, wid = tid >> 5;
    const int gr = lane >> 2, gc = lane & 3;
    const int m_w = (wid >> 2) * 64;
    const int n_w = (wid & 3) * 32;

    const int prow = tid >> 3;
    const int pkq = (tid & 7) * 4;

    float4 na[4], nb[4];

    auto loadAB = [&](int c) {
        const int k0 = c * KC;
        #pragma unroll
        for (int j = 0; j < 4; j++) {
            const int row = prow + 32 * j;
            na[j] = *reinterpret_cast<const float4*>(Abase + (size_t)row * a_rs + k0 + pkq);
            nb[j] = *reinterpret_cast<const float4*>(Bbase + (size_t)row * D + k0 + pkq);
        }
    };
    auto cvt_store = [&](__nv_bfloat16* hi, __nv_bfloat16* lo, int off, float4 v) {
        __nv_bfloat16 h0 = __float2bfloat16(v.x);
        __nv_bfloat16 h1 = __float2bfloat16(v.y);
        __nv_bfloat16 h2 = __float2bfloat16(v.z);
        __nv_bfloat16 h3 = __float2bfloat16(v.w);
        __nv_bfloat162 hp0 = {h0, h1}, hp1 = {h2, h3};
        __nv_bfloat162 lp0 = {__float2bfloat16(v.x - __bfloat162float(h0)),
                              __float2bfloat16(v.y - __bfloat162float(h1))};
        __nv_bfloat162 lp1 = {__float2bfloat16(v.z - __bfloat162float(h2)),
                              __float2bfloat16(v.w - __bfloat162float(h3))};
        *reinterpret_cast<__nv_bfloat162*>(hi + off) = hp0;
        *reinterpret_cast<__nv_bfloat162*>(hi + off + 2) = hp1;
        *reinterpret_cast<__nv_bfloat162*>(lo + off) = lp0;
        *reinterpret_cast<__nv_bfloat162*>(lo + off + 2) = lp1;
    };
    auto stsAB = [&](int s) {
        __nv_bfloat16* sAh = smh + s * SC_STAGE;
        __nv_bfloat16* sAl = sAh + SC_REG;
        __nv_bfloat16* sBh = sAl + SC_REG;
        __nv_bfloat16* sBl = sBh + SC_REG;
        #pragma unroll
        for (int j = 0; j < 4; j++) {
            const int off = (prow + 32 * j) * SC_PAD + pkq;
            cvt_store(sAh, sAl, off, na[j]);
            cvt_store(sBh, sBl, off, nb[j]);
        }
    };

    float acc[4][4][4];
    #pragma unroll
    for (int i = 0; i < 4; i++)
        #pragma unroll
        for (int j = 0; j < 4; j++)
            #pragma unroll
            for (int q = 0; q < 4; q++) acc[i][j][q] = 0.f;

    loadAB(0);
    stsAB(0);
    __syncthreads();

    for (int c = 0; c < NC; c++) {
        const int s = c & 1;
        if (c + 1 < NC) loadAB(c + 1);

        const __nv_bfloat16* sAh = smh + s * SC_STAGE;
        const __nv_bfloat16* sAl = sAh + SC_REG;
        const __nv_bfloat16* sBh = sAl + SC_REG;
        const __nv_bfloat16* sBl = sBh + SC_REG;

        #pragma unroll
        for (int ks = 0; ks < 2; ks++) {
            uint32_t ah[4][4], al[4][4], bh[4][2], bl[4][2];
            #pragma unroll
            for (int mf = 0; mf < 4; mf++) {
                const int base = (m_w + mf * 16 + gr) * SC_PAD + ks * 16 + 2 * gc;
                ah[mf][0] = *reinterpret_cast<const uint32_t*>(sAh + base);
                ah[mf][1] = *reinterpret_cast<const uint32_t*>(sAh + base + 8 * SC_PAD);
                ah[mf][2] = *reinterpret_cast<const uint32_t*>(sAh + base + 8);
                ah[mf][3] = *reinterpret_cast<const uint32_t*>(sAh + base + 8 * SC_PAD + 8);
                al[mf][0] = *reinterpret_cast<const uint32_t*>(sAl + base);
                al[mf][1] = *reinterpret_cast<const uint32_t*>(sAl + base + 8 * SC_PAD);
                al[mf][2] = *reinterpret_cast<const uint32_t*>(sAl + base + 8);
                al[mf][3] = *reinterpret_cast<const uint32_t*>(sAl + base + 8 * SC_PAD + 8);
            }
            #pragma unroll
            for (int nf = 0; nf < 4; nf++) {
                const int base = (n_w + nf * 8 + gr) * SC_PAD + ks * 16 + 2 * gc;
                bh[nf][0] = *reinterpret_cast<const uint32_t*>(sBh + base);
                bh[nf][1] = *reinterpret_cast<const uint32_t*>(sBh + base + 8);
                bl[nf][0] = *reinterpret_cast<const uint32_t*>(sBl + base);
                bl[nf][1] = *reinterpret_cast<const uint32_t*>(sBl + base + 8);
            }
            #pragma unroll
            for (int mf = 0; mf < 4; mf++)
                #pragma unroll
                for (int nf = 0; nf < 4; nf++)
                    mma16(acc[mf][nf], ah[mf], bh[nf]);
            #pragma unroll
            for (int mf = 0; mf < 4; mf++)
                #pragma unroll
                for (int nf = 0; nf < 4; nf++)
                    mma16(acc[mf][nf], al[mf], bh[nf]);
            #pragma unroll
            for (int mf = 0; mf < 4; mf++)
                #pragma unroll
                for (int nf = 0; nf < 4; nf++)
                    mma16(acc[mf][nf], ah[mf], bl[nf]);
        }
        if (c + 1 < NC) stsAB(s ^ 1);
        __syncthreads();
    }

    #pragma unroll
    for (int mf = 0; mf < 4; mf++)
        #pragma unroll
        for (int nf = 0; nf < 4; nf++) {
            const int mrow = m_w + mf * 16 + gr;
            const int ncol = n_w + nf * 8 + 2 * gc;
            float2 v0 = make_float2(acc[mf][nf][0], acc[mf][nf][1]);
            float2 v1 = make_float2(acc[mf][nf][2], acc[mf][nf][3]);
            *reinterpret_cast<float2*>(Cbase + (size_t)mrow * c_rs + ncol) = v0;
            *reinterpret_cast<float2*>(Cbase + (size_t)(mrow + 8) * c_rs + ncol) = v1;
        }
}

// ---------------------------------------------------------------------------
// AV GEMM split-BF16: out[t][b][d] = sum_s attn[b][t][s]*values[b][s][d]
// B staged as uint32 k-pair words: word[kp][n] = bf16x2(v[2kp][n], v[2kp+1][n]),
// row pad 136 words -> conflict-free consumer loads, vectorized producer STS.
// ---------------------------------------------------------------------------
static constexpr int AV_A_WPAD = 20;                       // words per A row (40 halves)
static constexpr int AV_A_WORDS = 128 * AV_A_WPAD;         // 2560 words / region
static constexpr int AV_B_WPAD = 136;                      // words per kp row
static constexpr int AV_B_WORDS = 16 * AV_B_WPAD;          // 2176 words / region
static constexpr int AV_STAGE_WORDS = 2 * AV_A_WORDS + 2 * AV_B_WORDS;  // 9472
static constexpr int AV_SMEM = 2 * AV_STAGE_WORDS * 4;     // 75776 bytes

__global__ __launch_bounds__(256) void k_gemm_av(const float* __restrict__ attn,
                                                 const float* __restrict__ values,
                                                 float* __restrict__ out) {
    extern __shared__ uint32_t smw[];
    constexpr int NC = S / KC;   // 64

    const int tid = threadIdx.x;
    const int n0 = blockIdx.x * 128;
    const int m0 = blockIdx.y * 128;
    const int bz = blockIdx.z;

    const float* Abase = attn + ((size_t)bz * T + m0) * S;
    const float* Bbase = values + (size_t)bz * S * D + n0;
    float* Cbase = out + (size_t)m0 * B * D + (size_t)bz * D + n0;
    const size_t c_rs = (size_t)B * D;

    const int lane = tid & 31, wid = tid >> 5;
    const int gr = lane >> 2, gc = lane & 3;
    const int m_w = (wid >> 2) * 64;
    const int n_w = (wid & 3) * 32;

    // A producer: row = tid>>3 (+32/pass), k-quad = (tid&7)*4
    const int prow = tid >> 3;
    const int pkq = (tid & 7) * 4;
    // B producer: kp = tid>>5 (+8 on pass 2), n-quad = (tid&31)*4
    const int bkp = tid >> 5;
    const int bnq = (tid & 31) * 4;

    float4 na[4];
    float4 vb0[2], vb1[2];

    auto loadAB = [&](int c) {
        const int k0 = c * KC;
        #pragma unroll
        for (int j = 0; j < 4; j++)
            na[j] = *reinterpret_cast<const float4*>(Abase + (size_t)(prow + 32 * j) * S + k0 + pkq);
        #pragma unroll
        for (int j = 0; j < 2; j++) {
            const int kk = k0 + 2 * (bkp + 8 * j);
            vb0[j] = *reinterpret_cast<const float4*>(Bbase + (size_t)kk * D + bnq);
            vb1[j] = *reinterpret_cast<const float4*>(Bbase + (size_t)(kk + 1) * D + bnq);
        }
    };
    auto stsAB = [&](int s) {
        uint32_t* sAh = smw + s * AV_STAGE_WORDS;
        uint32_t* sAl = sAh + AV_A_WORDS;
        uint32_t* sBh = sAl + AV_A_WORDS;
        uint32_t* sBl = sBh + AV_B_WORDS;
        #pragma unroll
        for (int j = 0; j < 4; j++) {
            const int w = (prow + 32 * j) * AV_A_WPAD + (pkq >> 1);
            const float4 v = na[j];
            __nv_bfloat16 h0 = __float2bfloat16(v.x);
            __nv_bfloat16 h1 = __float2bfloat16(v.y);
            __nv_bfloat16 h2 = __float2bfloat16(v.z);
            __nv_bfloat16 h3 = __float2bfloat16(v.w);
            uint2 hp, lp;
            __nv_bfloat162 t0 = {h0, h1}; hp.x = *reinterpret_cast<uint32_t*>(&t0);
            __nv_bfloat162 t1 = {h2, h3}; hp.y = *reinterpret_cast<uint32_t*>(&t1);
            lp.x = packbf(v.x - __bfloat162float(h0), v.y - __bfloat162float(h1));
            lp.y = packbf(v.z - __bfloat162float(h2), v.w - __bfloat162float(h3));
            *reinterpret_cast<uint2*>(sAh + w) = hp;
            *reinterpret_cast<uint2*>(sAl + w) = lp;
        }
        #pragma unroll
        for (int j = 0; j < 2; j++) {
            const int kp = bkp + 8 * j;
            const int w = kp * AV_B_WPAD + bnq;
            const float e0[4] = {vb0[j].x, vb0[j].y, vb0[j].z, vb0[j].w};
            const float e1[4] = {vb1[j].x, vb1[j].y, vb1[j].z, vb1[j].w};
            uint4 hw, lw;
            uint32_t* hwp = reinterpret_cast<uint32_t*>(&hw);
            uint32_t* lwp = reinterpret_cast<uint32_t*>(&lw);
            #pragma unroll
            for (int q = 0; q < 4; q++) {
                __nv_bfloat16 h0 = __float2bfloat16(e0[q]);
                __nv_bfloat16 h1 = __float2bfloat16(e1[q]);
                __nv_bfloat162 th = {h0, h1};
                hwp[q] = *reinterpret_cast<uint32_t*>(&th);
                lwp[q] = packbf(e0[q] - __bfloat162float(h0), e1[q] - __bfloat162float(h1));
            }
            *reinterpret_cast<uint4*>(sBh + w) = hw;
            *reinterpret_cast<uint4*>(sBl + w) = lw;
        }
    };

    float acc[4][4][4];
    #pragma unroll
    for (int i = 0; i < 4; i++)
        #pragma unroll
        for (int j = 0; j < 4; j++)
            #pragma unroll
            for (int q = 0; q < 4; q++) acc[i][j][q] = 0.f;

    loadAB(0);
    stsAB(0);
    __syncthreads();

    for (int c = 0; c < NC; c++) {
        const int s = c & 1;
        if (c + 1 < NC) loadAB(c + 1);

        const uint32_t* sAh = smw + s * AV_STAGE_WORDS;
        const uint32_t* sAl = sAh + AV_A_WORDS;
        const uint32_t* sBh = sAl + AV_A_WORDS;
        const uint32_t* sBl = sBh + AV_B_WORDS;

        #pragma unroll
        for (int ks = 0; ks < 2; ks++) {
            uint32_t ah[4][4], al[4][4], bh[4][2], bl[4][2];
            #pragma unroll
            for (int mf = 0; mf < 4; mf++) {
                const int m = m_w + mf * 16 + gr;
                const int base = m * AV_A_WPAD + ks * 8 + gc;
                ah[mf][0] = sAh[base];
                ah[mf][1] = sAh[base + 8 * AV_A_WPAD];
                ah[mf][2] = sAh[base + 4];
                ah[mf][3] = sAh[base + 8 * AV_A_WPAD + 4];
                al[mf][0] = sAl[base];
                al[mf][1] = sAl[base + 8 * AV_A_WPAD];
                al[mf][2] = sAl[base + 4];
                al[mf][3] = sAl[base + 8 * AV_A_WPAD + 4];
            }
            #pragma unroll
            for (int nf = 0; nf < 4; nf++) {
                const int n = n_w + nf * 8 + gr;
                const int b0 = (ks * 8 + gc) * AV_B_WPAD + n;
                const int b1 = (ks * 8 + gc + 4) * AV_B_WPAD + n;
                bh[nf][0] = sBh[b0];
                bh[nf][1] = sBh[b1];
                bl[nf][0] = sBl[b0];
                bl[nf][1] = sBl[b1];
            }
            #pragma unroll
            for (int mf = 0; mf < 4; mf++)
                #pragma unroll
                for (int nf = 0; nf < 4; nf++)
                    mma16(acc[mf][nf], ah[mf], bh[nf]);
            #pragma unroll
            for (int mf = 0; mf < 4; mf++)
                #pragma unroll
                for (int nf = 0; nf < 4; nf++)
                    mma16(acc[mf][nf], al[mf], bh[nf]);
            #pragma unroll
            for (int mf = 0; mf < 4; mf++)
                #pragma unroll
                for (int nf = 0; nf < 4; nf++)
                    mma16(acc[mf][nf], ah[mf], bl[nf]);
        }
        if (c + 1 < NC) stsAB(s ^ 1);
        __syncthreads();
    }

    #pragma unroll
    for (int mf = 0; mf < 4; mf++)
        #pragma unroll
        for (int nf = 0; nf < 4; nf++) {
            const int mrow = m_w + mf * 16 + gr;
            const int ncol = n_w + nf * 8 + 2 * gc;
            float2 v0 = make_float2(acc[mf][nf][0], acc[mf][nf][1]);
            float2 v1 = make_float2(acc[mf][nf][2], acc[mf][nf][3]);
            *reinterpret_cast<float2*>(Cbase + (size_t)mrow * c_rs + ncol) = v0;
            *reinterpret_cast<float2*>(Cbase + (size_t)(mrow + 8) * c_rs + ncol) = v1;
        }
}

// ---------------------------------------------------------------------------
// LayerNorm in place on g_X rows (B*T rows of D)
// ---------------------------------------------------------------------------
__global__ __launch_bounds__(256) void k_ln(const float* __restrict__ gamma,
                                            const float* __restrict__ beta) {
    const int row = blockIdx.x;
    float* x = &g_X[(size_t)row * D];
    const int tid = threadIdx.x;

    float2 v = *reinterpret_cast<const float2*>(&x[tid * 2]);
    float s = v.x + v.y;
    float q = v.x * v.x + v.y * v.y;

    __shared__ float sh_s[8], sh_q[8];
    #pragma unroll
    for (int o = 16; o > 0; o >>= 1) {
        s += __shfl_xor_sync(0xffffffffu, s, o);
        q += __shfl_xor_sync(0xffffffffu, q, o);
    }
    if ((tid & 31) == 0) { sh_s[tid >> 5] = s; sh_q[tid >> 5] = q; }
    __syncthreads();
    float ts = 0.f, tq = 0.f;
    #pragma unroll
    for (int i = 0; i < 8; i++) { ts += sh_s[i]; tq += sh_q[i]; }

    const float mean = ts * (1.0f / D);
    const float var = tq * (1.0f / D) - mean * mean;
    const float rstd = rsqrtf(var + LN_EPS);

    float2 g = *reinterpret_cast<const float2*>(&gamma[tid * 2]);
    float2 bb = *reinterpret_cast<const float2*>(&beta[tid * 2]);
    float2 o;
    o.x = g.x * (v.x - mean) * rstd + bb.x;
    o.y = g.y * (v.y - mean) * rstd + bb.y;
    *reinterpret_cast<float2*>(&x[tid * 2]) = o;
}

// ---------------------------------------------------------------------------
// Softmax over S for each of B*T rows, in place
// ---------------------------------------------------------------------------
__global__ __launch_bounds__(256) void k_softmax(float* __restrict__ attn) {
    const size_t row = blockIdx.x;
    float* p = attn + row * (size_t)S;
    const int tid = threadIdx.x;

    float4 v0 = reinterpret_cast<const float4*>(p)[tid * 2 + 0];
    float4 v1 = reinterpret_cast<const float4*>(p)[tid * 2 + 1];

    float m = fmaxf(fmaxf(fmaxf(v0.x, v0.y), fmaxf(v0.z, v0.w)),
                    fmaxf(fmaxf(v1.x, v1.y), fmaxf(v1.z, v1.w)));
    __shared__ float sh[8];
    #pragma unroll
    for (int o = 16; o > 0; o >>= 1) m = fmaxf(m, __shfl_xor_sync(0xffffffffu, m, o));
    if ((tid & 31) == 0) sh[tid >> 5] = m;
    __syncthreads();
    float gm = sh[0];
    #pragma unroll
    for (int i = 1; i < 8; i++) gm = fmaxf(gm, sh[i]);
    __syncthreads();

    v0.x = __expf(v0.x - gm); v0.y = __expf(v0.y - gm);
    v0.z = __expf(v0.z - gm); v0.w = __expf(v0.w - gm);
    v1.x = __expf(v1.x - gm); v1.y = __expf(v1.y - gm);
    v1.z = __expf(v1.z - gm); v1.w = __expf(v1.w - gm);

    float s = v0.x + v0.y + v0.z + v0.w + v1.x + v1.y + v1.z + v1.w;
    #pragma unroll
    for (int o = 16; o > 0; o >>= 1) s += __shfl_xor_sync(0xffffffffu, s, o);
    if ((tid & 31) == 0) sh[tid >> 5] = s;
    __syncthreads();
    float gs = 0.f;
    #pragma unroll
    for (int i = 0; i < 8; i++) gs += sh[i];
    const float inv = 1.0f / gs;

    v0.x *= inv; v0.y *= inv; v0.z *= inv; v0.w *= inv;
    v1.x *= inv; v1.y *= inv; v1.z *= inv; v1.w *= inv;
    reinterpret_cast<float4*>(p)[tid * 2 + 0] = v0;
    reinterpret_cast<float4*>(p)[tid * 2 + 1] = v1;
}

// ---------------------------------------------------------------------------
extern "C" void kernel_launch(void* const* d_in, const int* in_sizes, int n_in,
                              void* d_out, int out_size) {
    const float* inp    = (const float*)d_in[0];  // [T,B,D]
    const float* ctx    = (const float*)d_in[1];  // [B,S,D]
    const float* values = (const float*)d_in[2];  // [B,S,D]
    const float* W      = (const float*)d_in[3];  // [D,D]
    const float* gamma  = (const float*)d_in[4];  // [D]
    const float* beta   = (const float*)d_in[5];  // [D]

    float* out_wc   = (float*)d_out;                       // [T,B,D]
    float* out_attn = (float*)d_out + (size_t)T * B * D;   // [B*T,S]

    cudaFuncSetAttribute(k_gemm_nt<0>, cudaFuncAttributeMaxDynamicSharedMemorySize, SC_SMEM);
    cudaFuncSetAttribute(k_gemm_nt<1>, cudaFuncAttributeMaxDynamicSharedMemorySize, SC_SMEM);
    cudaFuncSetAttribute(k_gemm_av, cudaFuncAttributeMaxDynamicSharedMemorySize, AV_SMEM);

    // 1) linear: g_X = inp @ W^T (rows b*T+t)  [bf16x3]
    {
        dim3 grid(D / 128, (B * T) / 128, 1);
        k_gemm_nt<0><<<grid, 256, SC_SMEM>>>(inp, W, nullptr);
    }
    // 2) LayerNorm in place
    k_ln<<<B * T, 256>>>(gamma, beta);
    // 3) scores -> attn region  [bf16x3]
    {
        dim3 grid(S / 128, T / 128, B);
        k_gemm_nt<1><<<grid, 256, SC_SMEM>>>(nullptr, ctx, out_attn);
    }
    // 4) softmax in place
    k_softmax<<<B * T, 256>>>(out_attn);
    // 5) weightedContext  [bf16x3]
    {
        dim3 grid(D / 128, T / 128, B);
        k_gemm_av<<<grid, 256, AV_SMEM>>>(out_attn, values, out_wc);
    }
}